// round 1
// baseline (speedup 1.0000x reference)
#include <cuda_runtime.h>

// ---------------- problem constants ----------------
#define T_DIM 4
#define B_DIM 16
#define C_DIM 128
#define E_DIM 256
#define H_DIM 32
#define W_DIM 32
#define HW_DIM (H_DIM * W_DIM)
#define TB_DIM (T_DIM * B_DIM)
#define BN_EPS 1e-5f
#define LIF_TAU 0.5f

// ---------------- device scratch (no allocations allowed) ----------------
__device__ float g_spk[(size_t)T_DIM * B_DIM * E_DIM * HW_DIM];  // spikes buffer (67 MB)
__device__ float g_mem[(size_t)T_DIM * B_DIM * E_DIM * HW_DIM];  // conv+bn pre-LIF buffer (67 MB)
__device__ float g_w3f[E_DIM * C_DIM * 9];
__device__ float g_w4f[E_DIM * E_DIM * 9];
__device__ float g_wrf[E_DIM * C_DIM];
__device__ float g_bias3[E_DIM];
__device__ float g_bias4[E_DIM];
__device__ float g_biasr[E_DIM];

// ---------------- f32x2 packed-FMA helpers (sm_100+) ----------------
union F2U { float2 f2; unsigned long long u; };

__device__ __forceinline__ float2 fma2(float2 a, float2 b, float2 c) {
    F2U A, B, C, D;
    A.f2 = a; B.f2 = b; C.f2 = c;
    asm("fma.rn.f32x2 %0, %1, %2, %3;" : "=l"(D.u) : "l"(A.u), "l"(B.u), "l"(C.u));
    return D.f2;
}

__device__ __forceinline__ float2 lds2(const float* p) {
    return *reinterpret_cast<const float2*>(p);
}

// ---------------- BN folding ----------------
// wf[e, c, k] = w[e, c, k] * gamma[e] * rsqrt(var[e] + eps)
__global__ void fold_w_kernel(const float* __restrict__ w,
                              const float* __restrict__ g,
                              const float* __restrict__ v,
                              float* __restrict__ wf,
                              int cin_kk, int total) {
    int i = blockIdx.x * blockDim.x + threadIdx.x;
    if (i >= total) return;
    int e = i / cin_kk;
    float s = g[e] * rsqrtf(v[e] + BN_EPS);
    wf[i] = w[i] * s;
}

// bias[e] = beta[e] - mean[e] * scale[e]
__global__ void fold_b_kernel(const float* __restrict__ g,
                              const float* __restrict__ b,
                              const float* __restrict__ m,
                              const float* __restrict__ v,
                              float* __restrict__ bf) {
    int e = threadIdx.x;
    if (e < E_DIM) {
        float s = g[e] * rsqrtf(v[e] + BN_EPS);
        bf[e] = b[e] - m[e] * s;
    }
}

// ---------------- LIF: sequential over T, hard reset ----------------
__global__ void lif_kernel(const float* __restrict__ in,
                           float* __restrict__ out, int npt) {
    int i = blockIdx.x * blockDim.x + threadIdx.x;
    if (i >= npt) return;
    float mem = 0.0f;
#pragma unroll
    for (int t = 0; t < T_DIM; ++t) {
        mem = mem * LIF_TAU + in[(size_t)t * npt + i];
        bool fire = (mem >= 1.0f);            // spike_fn(mem - 1) with v>=0 -> 1
        out[(size_t)t * npt + i] = fire ? 1.0f : 0.0f;
        if (fire) mem = 0.0f;                 // hard reset: mem * (1 - s)
    }
}

// ---------------- direct conv (+folded BN, optional residual add) ----------------
// Block: one image n, 64 output channels, 8 rows x 32 cols of pixels.
// Thread: 8 out-channels x 8 pixels (4 f32x2 pairs).  FFMA2 inner loop.
template <int CIN, int KS, int CC>
__global__ void __launch_bounds__(256, 2)
conv_kernel(const float* __restrict__ in,
            const float* __restrict__ wf,
            const float* __restrict__ bias,
            const float* __restrict__ addend,   // optional (residual fuse)
            float* __restrict__ out) {
    constexpr int ROWS    = 8;
    constexpr int IN_ROWS = ROWS + KS - 1;
    constexpr int IN_COLS = 34;                 // padded: even stride, conflict-neutral
    constexpr int KK      = KS * KS;
    constexpr int IN_ELEMS = CC * IN_ROWS * IN_COLS;
    constexpr int W_ELEMS  = 64 * CC * KK;

    __shared__ __align__(16) float  s_in[IN_ELEMS];
    __shared__ __align__(16) float2 s_w[W_ELEMS];   // weights pre-duplicated {w, w}

    const int n  = blockIdx.z;
    const int eo = blockIdx.y * 64;
    const int r0 = blockIdx.x * ROWS;

    const int tid = threadIdx.x;
    const int eg  = tid >> 5;          // warp id: 8 e-values per warp (broadcast weights)
    const int pg  = tid & 31;
    const int rr  = pg >> 2;           // row within tile: 0..7
    const int x0  = (pg & 3) << 3;     // col base: 0,8,16,24

    float2 acc[8][4];
#pragma unroll
    for (int i = 0; i < 8; ++i)
#pragma unroll
        for (int j = 0; j < 4; ++j) acc[i][j] = make_float2(0.0f, 0.0f);

    for (int c0 = 0; c0 < CIN; c0 += CC) {
        __syncthreads();
        // ---- stage input tile (with halo + zero pad for KS==3) ----
        const float* inb = in + ((size_t)n * CIN + c0) * HW_DIM;
        for (int idx = tid; idx < IN_ELEMS; idx += 256) {
            int c   = idx / (IN_ROWS * IN_COLS);
            int rem = idx - c * (IN_ROWS * IN_COLS);
            int iy  = rem / IN_COLS;
            int ix  = rem - iy * IN_COLS;
            float val = 0.0f;
            if (KS == 3) {
                int gy = r0 + iy - 1;
                int gx = ix - 1;
                if ((unsigned)gy < (unsigned)H_DIM && (unsigned)gx < (unsigned)W_DIM)
                    val = inb[c * HW_DIM + gy * W_DIM + gx];
            } else {
                if (ix < W_DIM)
                    val = inb[c * HW_DIM + (r0 + iy) * W_DIM + ix];
            }
            s_in[idx] = val;
        }
        // ---- stage weights, duplicated into both f32x2 lanes ----
        for (int idx = tid; idx < W_ELEMS; idx += 256) {
            int e   = idx / (CC * KK);
            int rem = idx - e * (CC * KK);
            int c   = rem / KK;
            int k   = rem - c * KK;
            float wv = wf[((size_t)(eo + e) * CIN + (c0 + c)) * KK + k];
            s_w[idx] = make_float2(wv, wv);
        }
        __syncthreads();

        if (KS == 3) {
            for (int c = 0; c < CC; ++c) {
#pragma unroll
                for (int ky = 0; ky < 3; ++ky) {
                    const float* rowp = &s_in[(c * IN_ROWS + rr + ky) * IN_COLS + x0];
                    float2 q0 = lds2(rowp + 0);
                    float2 q1 = lds2(rowp + 2);
                    float2 q2 = lds2(rowp + 4);
                    float2 q3 = lds2(rowp + 6);
                    float2 q4 = lds2(rowp + 8);
                    float2 p0[4] = {q0, q1, q2, q3};                     // kx = 0
                    float2 p1[4] = {make_float2(q0.y, q1.x),             // kx = 1
                                    make_float2(q1.y, q2.x),
                                    make_float2(q2.y, q3.x),
                                    make_float2(q3.y, q4.x)};
                    float2 p2[4] = {q1, q2, q3, q4};                     // kx = 2
                    const float2* wrow = &s_w[(eg * 8) * (CC * KK) + c * KK + ky * 3];
#pragma unroll
                    for (int ee = 0; ee < 8; ++ee) {
                        float2 w0 = wrow[ee * CC * KK + 0];
                        float2 w1 = wrow[ee * CC * KK + 1];
                        float2 w2 = wrow[ee * CC * KK + 2];
#pragma unroll
                        for (int j = 0; j < 4; ++j) {
                            acc[ee][j] = fma2(w0, p0[j], acc[ee][j]);
                            acc[ee][j] = fma2(w1, p1[j], acc[ee][j]);
                            acc[ee][j] = fma2(w2, p2[j], acc[ee][j]);
                        }
                    }
                }
            }
        } else {  // KS == 1
            for (int c = 0; c < CC; ++c) {
                const float* rowp = &s_in[(c * IN_ROWS + rr) * IN_COLS + x0];
                float2 p[4] = {lds2(rowp + 0), lds2(rowp + 2),
                               lds2(rowp + 4), lds2(rowp + 6)};
                const float2* wp = &s_w[(eg * 8) * CC + c];
#pragma unroll
                for (int ee = 0; ee < 8; ++ee) {
                    float2 w = wp[ee * CC];
#pragma unroll
                    for (int j = 0; j < 4; ++j)
                        acc[ee][j] = fma2(w, p[j], acc[ee][j]);
                }
            }
        }
    }

    // ---- epilogue: + bias (folded BN), optional + residual, store ----
#pragma unroll
    for (int ee = 0; ee < 8; ++ee) {
        int e = eo + eg * 8 + ee;
        float b = bias[e];
        size_t obase = ((size_t)n * E_DIM + e) * HW_DIM + (size_t)(r0 + rr) * W_DIM + x0;
#pragma unroll
        for (int j = 0; j < 4; ++j) {
            float lo = acc[ee][j].x + b;
            float hi = acc[ee][j].y + b;
            if (addend) {
                lo += addend[obase + 2 * j];
                hi += addend[obase + 2 * j + 1];
            }
            out[obase + 2 * j]     = lo;
            out[obase + 2 * j + 1] = hi;
        }
    }
}

// ---------------- launch ----------------
extern "C" void kernel_launch(void* const* d_in, const int* in_sizes, int n_in,
                              void* d_out, int out_size) {
    const float* x  = (const float*)d_in[0];
    const float* w3 = (const float*)d_in[1];
    const float* g3 = (const float*)d_in[2];
    const float* b3 = (const float*)d_in[3];
    const float* m3 = (const float*)d_in[4];
    const float* v3 = (const float*)d_in[5];
    const float* w4 = (const float*)d_in[6];
    const float* g4 = (const float*)d_in[7];
    const float* b4 = (const float*)d_in[8];
    const float* m4 = (const float*)d_in[9];
    const float* v4 = (const float*)d_in[10];
    const float* wr = (const float*)d_in[11];
    const float* gr = (const float*)d_in[12];
    const float* br = (const float*)d_in[13];
    const float* mr = (const float*)d_in[14];
    const float* vr = (const float*)d_in[15];
    float* out = (float*)d_out;

    float *spk, *mem, *w3f, *w4f, *wrf, *bias3, *bias4, *biasr;
    cudaGetSymbolAddress((void**)&spk,   g_spk);
    cudaGetSymbolAddress((void**)&mem,   g_mem);
    cudaGetSymbolAddress((void**)&w3f,   g_w3f);
    cudaGetSymbolAddress((void**)&w4f,   g_w4f);
    cudaGetSymbolAddress((void**)&wrf,   g_wrf);
    cudaGetSymbolAddress((void**)&bias3, g_bias3);
    cudaGetSymbolAddress((void**)&bias4, g_bias4);
    cudaGetSymbolAddress((void**)&biasr, g_biasr);

    // fold BN into weights/bias
    fold_w_kernel<<<(E_DIM * C_DIM * 9 + 255) / 256, 256>>>(w3, g3, v3, w3f, C_DIM * 9, E_DIM * C_DIM * 9);
    fold_w_kernel<<<(E_DIM * E_DIM * 9 + 255) / 256, 256>>>(w4, g4, v4, w4f, E_DIM * 9, E_DIM * E_DIM * 9);
    fold_w_kernel<<<(E_DIM * C_DIM     + 255) / 256, 256>>>(wr, gr, vr, wrf, C_DIM,     E_DIM * C_DIM);
    fold_b_kernel<<<1, E_DIM>>>(g3, b3, m3, v3, bias3);
    fold_b_kernel<<<1, E_DIM>>>(g4, b4, m4, v4, bias4);
    fold_b_kernel<<<1, E_DIM>>>(gr, br, mr, vr, biasr);

    const int npt_c = B_DIM * C_DIM * HW_DIM;   // 2,097,152
    const int npt_e = B_DIM * E_DIM * HW_DIM;   // 4,194,304
    dim3 cgrid(H_DIM / 8, E_DIM / 64, TB_DIM);  // (4, 4, 64)

    // stage 0: LIF on raw input -> spikes (C=128)
    lif_kernel<<<(npt_c + 255) / 256, 256>>>(x, spk, npt_c);
    // conv3 (128->256) + BN -> membrane input
    conv_kernel<C_DIM, 3, 8><<<cgrid, 256>>>(spk, w3f, bias3, nullptr, mem);
    // LIF -> spikes (E=256)
    lif_kernel<<<(npt_e + 255) / 256, 256>>>(mem, spk, npt_e);
    // conv4 (256->256) + BN
    conv_kernel<E_DIM, 3, 8><<<cgrid, 256>>>(spk, w4f, bias4, nullptr, mem);
    // LIF -> spikes
    lif_kernel<<<(npt_e + 255) / 256, 256>>>(mem, spk, npt_e);
    // residual 1x1 conv on ORIGINAL x, + BN, + spikes -> d_out
    conv_kernel<C_DIM, 1, 16><<<cgrid, 256>>>(x, wrf, biasr, spk, out);
}